// round 1
// baseline (speedup 1.0000x reference)
#include <cuda_runtime.h>

#define BB 2
#define CC 64
#define CI 16
#define NN 6400          // 80*80
#define KS 5             // key splits
#define QB 128           // queries per block
#define KT 128           // key tile
#define NTILES (NN/KT)           // 50
#define TPS (NTILES/KS)          // tiles per split = 10

// Scratch (no allocations allowed)
__device__ float g_T[BB*NN*CI];        // theta  [b][n][16]
__device__ float g_P[BB*NN*CI];        // phi    [b][n][16]
__device__ float g_G[BB*NN*2*CI];      // g_x|g_bf [b][n][32]
__device__ float g_part[KS*BB*33*NN];  // partial acc(32)+wsum(1), [ks][b][j][n]

// Fast exp: magic-constant range reduction + degree-5 Taylor on FMA pipe.
// Valid for |s| < ~80; rel err ~2.4e-6.
__device__ __forceinline__ float fexp(float s) {
    float t  = s * 1.4426950408889634f;
    float kf = t + 12582912.0f;               // round-to-nearest via 1.5*2^23
    float nf = kf - 12582912.0f;
    float r  = fmaf(nf, -0.69314718055994531f, s);   // r in [-0.347, 0.347]
    float q  = 8.3333333e-3f;                  // 1/120
    q = fmaf(q, r, 4.1666666e-2f);             // 1/24
    q = fmaf(q, r, 1.6666666e-1f);             // 1/6
    q = fmaf(q, r, 5.0e-1f);
    q = fmaf(q, r, 1.0f);
    float e = fmaf(q, r, 1.0f);
    unsigned ib = ((unsigned)__float_as_int(kf) << 23) + 0x3F800000u;
    return e * __uint_as_float(ib);
}

// ---------------- Phase 1: theta/phi/g_x/g_bf projections ----------------
__global__ __launch_bounds__(128) void proj_kernel(
    const float* __restrict__ bfimg, const float* __restrict__ x,
    const float* __restrict__ w_theta, const float* __restrict__ b_theta,
    const float* __restrict__ w_phi,   const float* __restrict__ b_phi,
    const float* __restrict__ w_g,     const float* __restrict__ b_g,
    const float* __restrict__ w_gbf,   const float* __restrict__ b_gbf)
{
    // weights transposed to [c][i] so per-c reads are 4x LDS.128 broadcasts
    __shared__ float wT[CC*CI], wP[CC*CI], wG[CC*CI], wGB[CC*CI];
    int tid = threadIdx.x;
    for (int idx = tid; idx < CC*CI; idx += 128) {
        int i = idx / CC, c = idx % CC;
        wT[c*CI+i]  = w_theta[idx];
        wP[c*CI+i]  = w_phi[idx];
        wG[c*CI+i]  = w_g[idx];
        wGB[c*CI+i] = w_gbf[idx];
    }
    __syncthreads();

    int b = blockIdx.y;
    int n = blockIdx.x * 128 + tid;

    float at[CI], ap[CI], ag[CI], agb[CI];
    #pragma unroll
    for (int i = 0; i < CI; i++) {
        at[i] = b_theta[i]; ap[i] = b_phi[i];
        ag[i] = b_g[i];     agb[i] = b_gbf[i];
    }

    const float* bp = bfimg + (size_t)b*CC*NN + n;
    const float* xp = x     + (size_t)b*CC*NN + n;
    for (int c = 0; c < CC; c++) {
        float bv = bp[(size_t)c*NN];
        float xv = xp[(size_t)c*NN];
        #pragma unroll
        for (int i = 0; i < CI; i++) {
            at[i]  = fmaf(wT[c*CI+i],  bv, at[i]);
            ap[i]  = fmaf(wP[c*CI+i],  bv, ap[i]);
            agb[i] = fmaf(wGB[c*CI+i], bv, agb[i]);
            ag[i]  = fmaf(wG[c*CI+i],  xv, ag[i]);
        }
    }

    float* Tout = g_T + ((size_t)b*NN + n)*CI;
    float* Pout = g_P + ((size_t)b*NN + n)*CI;
    float* Gout = g_G + ((size_t)b*NN + n)*2*CI;
    #pragma unroll
    for (int i = 0; i < CI; i++) {
        Tout[i] = at[i];
        Pout[i] = ap[i];
        Gout[i] = ag[i];        // branch 1 values (from x)
        Gout[CI+i] = agb[i];    // branch 2 values (from bfimg)
    }
}

// ---------------- Phase 2: fused attention (no-max streaming softmax) ------
__global__ __launch_bounds__(128) void attn_kernel()
{
    __shared__ float sP[KT*CI];      // 8 KB
    __shared__ float sG[KT*2*CI];    // 16 KB

    int tid = threadIdx.x;
    int b   = blockIdx.z;
    int ks  = blockIdx.y;
    int q   = blockIdx.x * QB + tid;

    float th[CI];
    {
        const float4* Tq = (const float4*)(g_T + ((size_t)b*NN + q)*CI);
        #pragma unroll
        for (int i = 0; i < 4; i++) {
            float4 v = Tq[i];
            th[4*i+0]=v.x; th[4*i+1]=v.y; th[4*i+2]=v.z; th[4*i+3]=v.w;
        }
    }

    float acc[32];
    #pragma unroll
    for (int j = 0; j < 32; j++) acc[j] = 0.0f;
    float wsum = 0.0f;

    int k0base = ks * TPS * KT;

    for (int tile = 0; tile < TPS; tile++) {
        int k0 = k0base + tile * KT;
        // cooperative coalesced tile load
        {
            const float4* gp = (const float4*)(g_P + ((size_t)b*NN + k0)*CI);
            float4* sp4 = (float4*)sP;
            #pragma unroll
            for (int j = 0; j < (KT*CI/4)/128; j++)       // 4 iters
                sp4[tid + j*128] = gp[tid + j*128];
            const float4* gg = (const float4*)(g_G + ((size_t)b*NN + k0)*2*CI);
            float4* sg4 = (float4*)sG;
            #pragma unroll
            for (int j = 0; j < (KT*2*CI/4)/128; j++)     // 8 iters
                sg4[tid + j*128] = gg[tid + j*128];
        }
        __syncthreads();

        const float4* P4 = (const float4*)sP;
        const float4* G4 = (const float4*)sG;
        #pragma unroll 2
        for (int j = 0; j < KT; j++) {
            float4 p0 = P4[4*j+0], p1 = P4[4*j+1], p2 = P4[4*j+2], p3 = P4[4*j+3];
            float s0 =       th[0] *p0.x;
            s0 = fmaf(th[1], p0.y, s0); s0 = fmaf(th[2], p0.z, s0); s0 = fmaf(th[3], p0.w, s0);
            float s1 =       th[4] *p1.x;
            s1 = fmaf(th[5], p1.y, s1); s1 = fmaf(th[6], p1.z, s1); s1 = fmaf(th[7], p1.w, s1);
            float s2 =       th[8] *p2.x;
            s2 = fmaf(th[9], p2.y, s2); s2 = fmaf(th[10],p2.z, s2); s2 = fmaf(th[11],p2.w, s2);
            float s3 =       th[12]*p3.x;
            s3 = fmaf(th[13],p3.y, s3); s3 = fmaf(th[14],p3.z, s3); s3 = fmaf(th[15],p3.w, s3);
            float s = (s0 + s1) + (s2 + s3);

            float w = fexp(s);
            wsum += w;

            #pragma unroll
            for (int h = 0; h < 8; h++) {
                float4 g = G4[8*j+h];
                acc[4*h+0] = fmaf(w, g.x, acc[4*h+0]);
                acc[4*h+1] = fmaf(w, g.y, acc[4*h+1]);
                acc[4*h+2] = fmaf(w, g.z, acc[4*h+2]);
                acc[4*h+3] = fmaf(w, g.w, acc[4*h+3]);
            }
        }
        __syncthreads();
    }

    float* part = g_part + (size_t)(ks*BB + b)*33*NN + q;
    #pragma unroll
    for (int j = 0; j < 32; j++) part[(size_t)j*NN] = acc[j];
    part[(size_t)32*NN] = wsum;
}

// ---------------- Phase 3: combine partials + folded BN(W y) + residual ----
__global__ __launch_bounds__(128) void epi_kernel(
    const float* __restrict__ bfimg, const float* __restrict__ x,
    const float* __restrict__ w_W,   const float* __restrict__ b_W,
    const float* __restrict__ gamma, const float* __restrict__ beta,
    const float* __restrict__ mean,  const float* __restrict__ var,
    float* __restrict__ out)
{
    __shared__ float Wp[CC*CI];   // alpha[c] * w_W[c][ci]
    __shared__ float bp[CC];      // beta + alpha*(b_W - mean)
    int tid = threadIdx.x;
    if (tid < CC) {
        float inv = rsqrtf(var[tid] + 1e-5f);
        float al  = gamma[tid] * inv;
        bp[tid]   = beta[tid] + al * (b_W[tid] - mean[tid]);
    }
    for (int idx = tid; idx < CC*CI; idx += 128) {
        int c = idx / CI;
        float inv = rsqrtf(var[c] + 1e-5f);
        Wp[idx] = gamma[c] * inv * w_W[idx];
    }
    __syncthreads();

    int b = blockIdx.y;
    int n = blockIdx.x * 128 + tid;

    float y[32];
    float ws = 0.0f;
    #pragma unroll
    for (int j = 0; j < 32; j++) {
        float v = 0.0f;
        #pragma unroll
        for (int ksi = 0; ksi < KS; ksi++)
            v += g_part[((size_t)(ksi*BB + b)*33 + j)*NN + n];
        y[j] = v;
    }
    #pragma unroll
    for (int ksi = 0; ksi < KS; ksi++)
        ws += g_part[((size_t)(ksi*BB + b)*33 + 32)*NN + n];

    float invws = 1.0f / ws;
    #pragma unroll
    for (int j = 0; j < 32; j++) y[j] *= invws;

    const float* xr = x     + (size_t)b*CC*NN + n;
    const float* br = bfimg + (size_t)b*CC*NN + n;
    float* o1 = out + (size_t)b*2*CC*NN + n;
    float* o2 = o1 + (size_t)CC*NN;

    for (int c = 0; c < CC; c++) {
        const float4* w4 = (const float4*)&Wp[c*CI];
        float4 wa = w4[0], wb = w4[1], wc = w4[2], wd = w4[3];
        float base = bp[c];
        float r1 = base + xr[(size_t)c*NN];
        float r2 = base + br[(size_t)c*NN];
        r1 = fmaf(wa.x, y[0],  r1); r1 = fmaf(wa.y, y[1],  r1);
        r1 = fmaf(wa.z, y[2],  r1); r1 = fmaf(wa.w, y[3],  r1);
        r1 = fmaf(wb.x, y[4],  r1); r1 = fmaf(wb.y, y[5],  r1);
        r1 = fmaf(wb.z, y[6],  r1); r1 = fmaf(wb.w, y[7],  r1);
        r1 = fmaf(wc.x, y[8],  r1); r1 = fmaf(wc.y, y[9],  r1);
        r1 = fmaf(wc.z, y[10], r1); r1 = fmaf(wc.w, y[11], r1);
        r1 = fmaf(wd.x, y[12], r1); r1 = fmaf(wd.y, y[13], r1);
        r1 = fmaf(wd.z, y[14], r1); r1 = fmaf(wd.w, y[15], r1);
        r2 = fmaf(wa.x, y[16], r2); r2 = fmaf(wa.y, y[17], r2);
        r2 = fmaf(wa.z, y[18], r2); r2 = fmaf(wa.w, y[19], r2);
        r2 = fmaf(wb.x, y[20], r2); r2 = fmaf(wb.y, y[21], r2);
        r2 = fmaf(wb.z, y[22], r2); r2 = fmaf(wb.w, y[23], r2);
        r2 = fmaf(wc.x, y[24], r2); r2 = fmaf(wc.y, y[25], r2);
        r2 = fmaf(wc.z, y[26], r2); r2 = fmaf(wc.w, y[27], r2);
        r2 = fmaf(wd.x, y[28], r2); r2 = fmaf(wd.y, y[29], r2);
        r2 = fmaf(wd.z, y[30], r2); r2 = fmaf(wd.w, y[31], r2);
        o1[(size_t)c*NN] = r1;
        o2[(size_t)c*NN] = r2;
    }
}

extern "C" void kernel_launch(void* const* d_in, const int* in_sizes, int n_in,
                              void* d_out, int out_size)
{
    (void)in_sizes; (void)n_in; (void)out_size;
    const float* bfimg   = (const float*)d_in[0];
    const float* x       = (const float*)d_in[1];
    const float* w_theta = (const float*)d_in[2];
    const float* b_theta = (const float*)d_in[3];
    const float* w_phi   = (const float*)d_in[4];
    const float* b_phi   = (const float*)d_in[5];
    const float* w_g     = (const float*)d_in[6];
    const float* b_g     = (const float*)d_in[7];
    const float* w_gbf   = (const float*)d_in[8];
    const float* b_gbf   = (const float*)d_in[9];
    const float* w_W     = (const float*)d_in[10];
    const float* b_W     = (const float*)d_in[11];
    const float* gamma   = (const float*)d_in[12];
    const float* beta    = (const float*)d_in[13];
    const float* mean    = (const float*)d_in[14];
    const float* var     = (const float*)d_in[15];
    float* out = (float*)d_out;

    dim3 g1(NN/128, BB);
    proj_kernel<<<g1, 128>>>(bfimg, x, w_theta, b_theta, w_phi, b_phi,
                             w_g, b_g, w_gbf, b_gbf);

    dim3 g2(NN/QB, KS, BB);
    attn_kernel<<<g2, 128>>>();

    dim3 g3(NN/128, BB);
    epi_kernel<<<g3, 128>>>(bfimg, x, w_W, b_W, gamma, beta, mean, var, out);
}

// round 2
// speedup vs baseline: 1.1776x; 1.1776x over previous
#include <cuda_runtime.h>

#define BB 2
#define CC 64
#define CI 16
#define NN 6400          // 80*80
#define KS 5             // key splits
#define QB 64            // queries per block (64 threads)
#define KT 128           // key tile
#define TPS 10           // tiles per split (NN/KT/KS)

typedef unsigned long long ull;

// Scratch (no allocations allowed)
__device__ float g_T[BB*NN*CI];        // theta  [b][n][16]
__device__ float g_P[BB*CI*NN];        // phi    [b][i][n]  (transposed!)
__device__ float g_G[BB*NN*2*CI];      // g_x|g_bf [b][n][32]
__device__ float g_part[KS*BB*33*NN];  // partial acc(32)+wsum(1), [ks][b][j][n]

// ---------------- f32x2 packed helpers (Blackwell FFMA2 path) ----------------
__device__ __forceinline__ ull fma2(ull a, ull b, ull c) {
    ull d; asm("fma.rn.f32x2 %0,%1,%2,%3;" : "=l"(d) : "l"(a), "l"(b), "l"(c));
    return d;
}
__device__ __forceinline__ ull mul2(ull a, ull b) {
    ull d; asm("mul.rn.f32x2 %0,%1,%2;" : "=l"(d) : "l"(a), "l"(b));
    return d;
}
__device__ __forceinline__ ull add2(ull a, ull b) {
    ull d; asm("add.rn.f32x2 %0,%1,%2;" : "=l"(d) : "l"(a), "l"(b));
    return d;
}
__device__ __forceinline__ ull dup2(float w) {
    ull d; asm("mov.b64 %0,{%1,%1};" : "=l"(d) : "f"(w));
    return d;
}
__device__ __forceinline__ ull pk2(float f) {
    unsigned u = __float_as_uint(f);
    return ((ull)u << 32) | u;
}

// Packed fast exp: magic range reduction + deg-5 Taylor, 2 lanes per instr.
// Int exponent construction rides the ALU pipe.
__device__ __forceinline__ ull fexp2(ull s) {
    ull t  = mul2(s, pk2(1.4426950408889634f));
    ull kf = add2(t, pk2(12582912.0f));
    ull nf = add2(kf, pk2(-12582912.0f));
    ull r  = fma2(nf, pk2(-0.69314718055994531f), s);
    ull q  = pk2(8.3333333e-3f);
    q = fma2(q, r, pk2(4.1666666e-2f));
    q = fma2(q, r, pk2(1.6666666e-1f));
    q = fma2(q, r, pk2(0.5f));
    q = fma2(q, r, pk2(1.0f));
    ull e = fma2(q, r, pk2(1.0f));
    unsigned klo = (unsigned)kf, khi = (unsigned)(kf >> 32);
    unsigned slo = (klo << 23) + 0x3F800000u;
    unsigned shi = (khi << 23) + 0x3F800000u;
    ull sc = ((ull)shi << 32) | slo;
    return mul2(e, sc);
}

// ---------------- Phase 1: projections, warp-per-projection ----------------
__global__ __launch_bounds__(128) void proj_kernel(
    const float* __restrict__ bfimg, const float* __restrict__ x,
    const float* __restrict__ w_theta, const float* __restrict__ b_theta,
    const float* __restrict__ w_phi,   const float* __restrict__ b_phi,
    const float* __restrict__ w_g,     const float* __restrict__ b_g,
    const float* __restrict__ w_gbf,   const float* __restrict__ b_gbf)
{
    // weights transposed to [proj][c][i]
    __shared__ __align__(16) float wS[4][CC*CI];
    int tid = threadIdx.x;
    for (int idx = tid; idx < CC*CI; idx += 128) {
        int i = idx / CC, c = idx % CC;
        wS[0][c*CI+i] = w_theta[idx];
        wS[1][c*CI+i] = w_phi[idx];
        wS[2][c*CI+i] = w_g[idx];
        wS[3][c*CI+i] = w_gbf[idx];
    }
    __syncthreads();

    int w    = tid >> 5;
    int lane = tid & 31;
    int b    = blockIdx.y;
    int n    = blockIdx.x * 32 + lane;

    const float* src  = ((w == 2) ? x : bfimg) + (size_t)b*CC*NN + n;
    const float* bias = (w == 0) ? b_theta : (w == 1) ? b_phi : (w == 2) ? b_g : b_gbf;
    const float* wm   = wS[w];

    float a[CI];
    #pragma unroll
    for (int i = 0; i < CI; i++) a[i] = bias[i];

    #pragma unroll 8
    for (int c = 0; c < CC; c++) {
        float v = __ldg(&src[(size_t)c*NN]);
        #pragma unroll
        for (int i = 0; i < CI; i++)
            a[i] = fmaf(wm[c*CI+i], v, a[i]);
    }

    if (w == 0) {
        float* o = g_T + ((size_t)b*NN + n)*CI;
        #pragma unroll
        for (int i = 0; i < CI; i++) o[i] = a[i];
    } else if (w == 1) {
        float* o = g_P + (size_t)b*CI*NN + n;
        #pragma unroll
        for (int i = 0; i < CI; i++) o[(size_t)i*NN] = a[i];
    } else if (w == 2) {
        float* o = g_G + ((size_t)b*NN + n)*2*CI;
        #pragma unroll
        for (int i = 0; i < CI; i++) o[i] = a[i];
    } else {
        float* o = g_G + ((size_t)b*NN + n)*2*CI + CI;
        #pragma unroll
        for (int i = 0; i < CI; i++) o[i] = a[i];
    }
}

// ---------------- Phase 2: fused attention, f32x2 packed ----------------
__global__ __launch_bounds__(64) void attn_kernel()
{
    __shared__ __align__(16) float sPt[CI*KT];    // [dim][key], 8 KB
    __shared__ __align__(16) float sG[KT*2*CI];   // [key][32ch], 16 KB

    int tid = threadIdx.x;
    int b   = blockIdx.z;
    int ks  = blockIdx.y;
    int q   = blockIdx.x * QB + tid;

    // theta for my query, duplicated into packed pairs
    ull th2[CI];
    {
        const float4* Tq = (const float4*)(g_T + ((size_t)b*NN + q)*CI);
        #pragma unroll
        for (int i = 0; i < 4; i++) {
            float4 v = Tq[i];
            th2[4*i+0] = dup2(v.x); th2[4*i+1] = dup2(v.y);
            th2[4*i+2] = dup2(v.z); th2[4*i+3] = dup2(v.w);
        }
    }

    ull acc2[16];
    #pragma unroll
    for (int j = 0; j < 16; j++) acc2[j] = 0ull;
    ull wsum2 = 0ull;

    int k0base = ks * TPS * KT;

    for (int tile = 0; tile < TPS; tile++) {
        int k0 = k0base + tile * KT;
        {
            // phi tile: g_P is [b][i][n] so each dim row is contiguous
            const float4* gp = (const float4*)(g_P + (size_t)b*CI*NN + k0);
            float4* sp4 = (float4*)sPt;
            #pragma unroll
            for (int t = 0; t < 8; t++) {          // 512 float4 / 64 thr
                int idx = tid + t*64;
                int i = idx >> 5, jj = idx & 31;
                sp4[i*32 + jj] = gp[(size_t)i*(NN/4) + jj];
            }
            const float4* gg = (const float4*)(g_G + ((size_t)b*NN + k0)*2*CI);
            float4* sg4 = (float4*)sG;
            #pragma unroll
            for (int t = 0; t < 16; t++)           // 1024 float4 / 64 thr
                sg4[tid + t*64] = gg[tid + t*64];
        }
        __syncthreads();

        #pragma unroll 1
        for (int j4 = 0; j4 < KT; j4 += 4) {
            // scores for 4 keys, packed as (s0,s1),(s2,s3)
            ulonglong2 pp0 = *(const ulonglong2*)(sPt + 0*KT + j4);
            ull s01 = mul2(th2[0], pp0.x);
            ull s23 = mul2(th2[0], pp0.y);
            #pragma unroll
            for (int i = 1; i < CI; i++) {
                ulonglong2 pp = *(const ulonglong2*)(sPt + i*KT + j4);
                s01 = fma2(th2[i], pp.x, s01);
                s23 = fma2(th2[i], pp.y, s23);
            }

            ull w01 = fexp2(s01);
            ull w23 = fexp2(s23);
            wsum2 = add2(wsum2, add2(w01, w23));

            float wv[4];
            wv[0] = __uint_as_float((unsigned)w01);
            wv[1] = __uint_as_float((unsigned)(w01 >> 32));
            wv[2] = __uint_as_float((unsigned)w23);
            wv[3] = __uint_as_float((unsigned)(w23 >> 32));

            #pragma unroll
            for (int jj = 0; jj < 4; jj++) {
                ull wd = dup2(wv[jj]);
                const ulonglong2* gb = (const ulonglong2*)(sG + (j4+jj)*2*CI);
                #pragma unroll
                for (int h = 0; h < 8; h++) {
                    ulonglong2 gv = gb[h];
                    acc2[2*h+0] = fma2(wd, gv.x, acc2[2*h+0]);
                    acc2[2*h+1] = fma2(wd, gv.y, acc2[2*h+1]);
                }
            }
        }
        __syncthreads();
    }

    float* part = g_part + (size_t)(ks*BB + b)*33*NN + q;
    #pragma unroll
    for (int h = 0; h < 16; h++) {
        part[(size_t)(2*h+0)*NN] = __uint_as_float((unsigned)acc2[h]);
        part[(size_t)(2*h+1)*NN] = __uint_as_float((unsigned)(acc2[h] >> 32));
    }
    part[(size_t)32*NN] = __uint_as_float((unsigned)wsum2)
                        + __uint_as_float((unsigned)(wsum2 >> 32));
}

// ---------------- Phase 3: combine partials + folded BN(W y) + residual ----
__global__ __launch_bounds__(128) void epi_kernel(
    const float* __restrict__ bfimg, const float* __restrict__ x,
    const float* __restrict__ w_W,   const float* __restrict__ b_W,
    const float* __restrict__ gamma, const float* __restrict__ beta,
    const float* __restrict__ mean,  const float* __restrict__ var,
    float* __restrict__ out)
{
    __shared__ __align__(16) float Wp[CC*CI];   // alpha[c] * w_W[c][ci]
    __shared__ float bp[CC];                    // beta + alpha*(b_W - mean)
    int tid = threadIdx.x;
    if (tid < CC) {
        float inv = rsqrtf(var[tid] + 1e-5f);
        float al  = gamma[tid] * inv;
        bp[tid]   = beta[tid] + al * (b_W[tid] - mean[tid]);
    }
    for (int idx = tid; idx < CC*CI; idx += 128) {
        int c = idx / CI;
        float inv = rsqrtf(var[c] + 1e-5f);
        Wp[idx] = gamma[c] * inv * w_W[idx];
    }
    __syncthreads();

    int b = blockIdx.y;
    int n = blockIdx.x * 128 + tid;

    float y[32];
    float ws = 0.0f;
    #pragma unroll
    for (int j = 0; j < 32; j++) {
        float v = 0.0f;
        #pragma unroll
        for (int ksi = 0; ksi < KS; ksi++)
            v += g_part[((size_t)(ksi*BB + b)*33 + j)*NN + n];
        y[j] = v;
    }
    #pragma unroll
    for (int ksi = 0; ksi < KS; ksi++)
        ws += g_part[((size_t)(ksi*BB + b)*33 + 32)*NN + n];

    float invws = 1.0f / ws;
    #pragma unroll
    for (int j = 0; j < 32; j++) y[j] *= invws;

    const float* xr = x     + (size_t)b*CC*NN + n;
    const float* br = bfimg + (size_t)b*CC*NN + n;
    float* o1 = out + (size_t)b*2*CC*NN + n;
    float* o2 = o1 + (size_t)CC*NN;

    for (int c = 0; c < CC; c++) {
        const float4* w4 = (const float4*)&Wp[c*CI];
        float4 wa = w4[0], wb = w4[1], wc = w4[2], wd = w4[3];
        float base = bp[c];
        float r1 = base + xr[(size_t)c*NN];
        float r2 = base + br[(size_t)c*NN];
        r1 = fmaf(wa.x, y[0],  r1); r1 = fmaf(wa.y, y[1],  r1);
        r1 = fmaf(wa.z, y[2],  r1); r1 = fmaf(wa.w, y[3],  r1);
        r1 = fmaf(wb.x, y[4],  r1); r1 = fmaf(wb.y, y[5],  r1);
        r1 = fmaf(wb.z, y[6],  r1); r1 = fmaf(wb.w, y[7],  r1);
        r1 = fmaf(wc.x, y[8],  r1); r1 = fmaf(wc.y, y[9],  r1);
        r1 = fmaf(wc.z, y[10], r1); r1 = fmaf(wc.w, y[11], r1);
        r1 = fmaf(wd.x, y[12], r1); r1 = fmaf(wd.y, y[13], r1);
        r1 = fmaf(wd.z, y[14], r1); r1 = fmaf(wd.w, y[15], r1);
        r2 = fmaf(wa.x, y[16], r2); r2 = fmaf(wa.y, y[17], r2);
        r2 = fmaf(wa.z, y[18], r2); r2 = fmaf(wa.w, y[19], r2);
        r2 = fmaf(wb.x, y[20], r2); r2 = fmaf(wb.y, y[21], r2);
        r2 = fmaf(wb.z, y[22], r2); r2 = fmaf(wb.w, y[23], r2);
        r2 = fmaf(wc.x, y[24], r2); r2 = fmaf(wc.y, y[25], r2);
        r2 = fmaf(wc.z, y[26], r2); r2 = fmaf(wc.w, y[27], r2);
        r2 = fmaf(wd.x, y[28], r2); r2 = fmaf(wd.y, y[29], r2);
        r2 = fmaf(wd.z, y[30], r2); r2 = fmaf(wd.w, y[31], r2);
        o1[(size_t)c*NN] = r1;
        o2[(size_t)c*NN] = r2;
    }
}

extern "C" void kernel_launch(void* const* d_in, const int* in_sizes, int n_in,
                              void* d_out, int out_size)
{
    (void)in_sizes; (void)n_in; (void)out_size;
    const float* bfimg   = (const float*)d_in[0];
    const float* x       = (const float*)d_in[1];
    const float* w_theta = (const float*)d_in[2];
    const float* b_theta = (const float*)d_in[3];
    const float* w_phi   = (const float*)d_in[4];
    const float* b_phi   = (const float*)d_in[5];
    const float* w_g     = (const float*)d_in[6];
    const float* b_g     = (const float*)d_in[7];
    const float* w_gbf   = (const float*)d_in[8];
    const float* b_gbf   = (const float*)d_in[9];
    const float* w_W     = (const float*)d_in[10];
    const float* b_W     = (const float*)d_in[11];
    const float* gamma   = (const float*)d_in[12];
    const float* beta    = (const float*)d_in[13];
    const float* mean    = (const float*)d_in[14];
    const float* var     = (const float*)d_in[15];
    float* out = (float*)d_out;

    dim3 g1(NN/32, BB);
    proj_kernel<<<g1, 128>>>(bfimg, x, w_theta, b_theta, w_phi, b_phi,
                             w_g, b_g, w_gbf, b_gbf);

    dim3 g2(NN/QB, KS, BB);
    attn_kernel<<<g2, 64>>>();

    dim3 g3(NN/128, BB);
    epi_kernel<<<g3, 128>>>(bfimg, x, w_W, b_W, gamma, beta, mean, var, out);
}

// round 4
// speedup vs baseline: 3.1058x; 2.6375x over previous
#include <cuda_runtime.h>
#include <cuda_bf16.h>
#include <cstdint>

#define BB 2
#define CC 64
#define CI 16
#define NN 6400            // 80*80
#define KSP 25             // partial slots (key chunks of 256)
#define NITEMS 2500        // 50 qtiles * 2 batches * 25 kchunks
#define ATTN_BLOCKS 456    // 3 per SM (152 SMs on GB300)

typedef unsigned long long ull;
typedef unsigned int u32;

// ---- global scratch (no allocations allowed) ----
__device__ u32  g_Tb[BB*NN*8];              // theta bf16x2 words [b][q][8]
__device__ u32  g_Pb[BB*NN*8];              // phi   bf16x2 words [b][k][8]
__device__ __nv_bfloat16 g_Gv[(size_t)BB*NN*32]; // values [b][n][32ch]
__device__ float g_part[(size_t)KSP*BB*33*NN];   // partials acc(32)+wsum
__device__ unsigned g_ctr;

// =================== low-level helpers ===================
__device__ __forceinline__ u32 smem_u32(const void* p) {
    u32 a; asm("{ .reg .u64 t; cvta.to.shared.u64 t, %1; cvt.u32.u64 %0, t; }"
               : "=r"(a) : "l"(p));
    return a;
}
__device__ __forceinline__ void cp16(u32 dst, const void* src) {
    asm volatile("cp.async.cg.shared.global [%0], [%1], 16;" :: "r"(dst), "l"(src));
}
#define CP_COMMIT() asm volatile("cp.async.commit_group;" ::: "memory")
#define CP_WAIT(n)  asm volatile("cp.async.wait_group %0;" :: "n"(n) : "memory")

__device__ __forceinline__ void ldsm_x4(u32& r0, u32& r1, u32& r2, u32& r3, u32 a) {
    asm volatile("ldmatrix.sync.aligned.m8n8.x4.shared.b16 {%0,%1,%2,%3}, [%4];"
                 : "=r"(r0), "=r"(r1), "=r"(r2), "=r"(r3) : "r"(a));
}
__device__ __forceinline__ void ldsm_x4t(u32& r0, u32& r1, u32& r2, u32& r3, u32 a) {
    asm volatile("ldmatrix.sync.aligned.m8n8.x4.trans.shared.b16 {%0,%1,%2,%3}, [%4];"
                 : "=r"(r0), "=r"(r1), "=r"(r2), "=r"(r3) : "r"(a));
}
__device__ __forceinline__ void mma_bf16(float* d, const u32* a, const u32* b) {
    asm volatile(
        "mma.sync.aligned.m16n8k16.row.col.f32.bf16.bf16.f32 "
        "{%0,%1,%2,%3}, {%4,%5,%6,%7}, {%8,%9}, {%0,%1,%2,%3};"
        : "+f"(d[0]), "+f"(d[1]), "+f"(d[2]), "+f"(d[3])
        : "r"(a[0]), "r"(a[1]), "r"(a[2]), "r"(a[3]), "r"(b[0]), "r"(b[1]));
}

// ---------------- f32x2 packed fast exp ----------------
__device__ __forceinline__ ull fma2(ull a, ull b, ull c) {
    ull d; asm("fma.rn.f32x2 %0,%1,%2,%3;" : "=l"(d) : "l"(a), "l"(b), "l"(c)); return d;
}
__device__ __forceinline__ ull mul2(ull a, ull b) {
    ull d; asm("mul.rn.f32x2 %0,%1,%2;" : "=l"(d) : "l"(a), "l"(b)); return d;
}
__device__ __forceinline__ ull add2(ull a, ull b) {
    ull d; asm("add.rn.f32x2 %0,%1,%2;" : "=l"(d) : "l"(a), "l"(b)); return d;
}
__device__ __forceinline__ ull pk2(float f) {
    unsigned u = __float_as_uint(f); return ((ull)u << 32) | u;
}
__device__ __forceinline__ ull fexp2(ull s) {
    ull t  = mul2(s, pk2(1.4426950408889634f));
    ull kf = add2(t, pk2(12582912.0f));
    ull nf = add2(kf, pk2(-12582912.0f));
    ull r  = fma2(nf, pk2(-0.69314718055994531f), s);
    ull q  = pk2(8.3333333e-3f);
    q = fma2(q, r, pk2(4.1666666e-2f));
    q = fma2(q, r, pk2(1.6666666e-1f));
    q = fma2(q, r, pk2(0.5f));
    q = fma2(q, r, pk2(1.0f));
    ull e = fma2(q, r, pk2(1.0f));
    unsigned klo = (unsigned)kf, khi = (unsigned)(kf >> 32);
    unsigned slo = (klo << 23) + 0x3F800000u;
    unsigned shi = (khi << 23) + 0x3F800000u;
    return mul2(e, ((ull)shi << 32) | slo);
}
// pack f32x2 (lo,hi) -> bf16x2 word {lo | hi<<16}
__device__ __forceinline__ u32 packbf(ull e2) {
    u32 lo, hi, w;
    asm("mov.b64 {%0,%1}, %2;" : "=r"(lo), "=r"(hi) : "l"(e2));
    asm("cvt.rn.bf16x2.f32 %0, %1, %2;"
        : "=r"(w) : "f"(__uint_as_float(hi)), "f"(__uint_as_float(lo)));
    return w;
}

// ================== Phase 1: projections (bf16 out) ==================
__global__ __launch_bounds__(128) void proj_kernel(
    const float* __restrict__ bfimg, const float* __restrict__ x,
    const float* __restrict__ w_theta, const float* __restrict__ b_theta,
    const float* __restrict__ w_phi,   const float* __restrict__ b_phi,
    const float* __restrict__ w_g,     const float* __restrict__ b_g,
    const float* __restrict__ w_gbf,   const float* __restrict__ b_gbf)
{
    __shared__ __align__(16) float wS[4][CC*CI];
    __shared__ __align__(16) float sB[CC*32];
    __shared__ __align__(16) float sX[CC*32];
    int tid = threadIdx.x;
    for (int idx = tid; idx < CC*CI; idx += 128) {
        int i = idx / CC, c = idx % CC;
        wS[0][c*CI+i] = w_theta[idx];
        wS[1][c*CI+i] = w_phi[idx];
        wS[2][c*CI+i] = w_g[idx];
        wS[3][c*CI+i] = w_gbf[idx];
    }
    int b  = blockIdx.y;
    int n0 = blockIdx.x * 32;
    {
        const float4* gb = (const float4*)(bfimg + (size_t)b*CC*NN + n0);
        const float4* gx = (const float4*)(x     + (size_t)b*CC*NN + n0);
        #pragma unroll
        for (int k = 0; k < 4; k++) {
            int idx = tid + k*128;
            int c = idx >> 3, f = idx & 7;
            ((float4*)sB)[c*8 + f] = gb[(size_t)c*(NN/4) + f];
            ((float4*)sX)[c*8 + f] = gx[(size_t)c*(NN/4) + f];
        }
    }
    __syncthreads();

    int w = tid >> 5, lane = tid & 31;
    int n = n0 + lane;
    const float* src  = (w == 2) ? sX : sB;
    const float* bias = (w == 0) ? b_theta : (w == 1) ? b_phi : (w == 2) ? b_g : b_gbf;
    const float* wm   = wS[w];

    float a[CI];
    #pragma unroll
    for (int i = 0; i < CI; i++) a[i] = bias[i];
    #pragma unroll 8
    for (int c = 0; c < CC; c++) {
        float v = src[c*32 + lane];
        #pragma unroll
        for (int i = 0; i < CI; i++)
            a[i] = fmaf(wm[c*CI+i], v, a[i]);
    }

    u32 words[8];
    #pragma unroll
    for (int i = 0; i < 8; i++)
        asm("cvt.rn.bf16x2.f32 %0, %1, %2;" : "=r"(words[i]) : "f"(a[2*i+1]), "f"(a[2*i]));

    if (w < 2) {
        u32* o = ((w == 0) ? g_Tb : g_Pb) + ((size_t)b*NN + n)*8;
        #pragma unroll
        for (int i = 0; i < 8; i++) o[i] = words[i];
    } else {
        // values: [b][n][32ch], w==2 -> ch 0-15, w==3 -> ch 16-31
        u32* o = (u32*)(g_Gv + ((size_t)b*NN + n)*32) + (w - 2)*8;
        #pragma unroll
        for (int i = 0; i < 8; i++) o[i] = words[i];
    }
}

// ================== Phase 2: HMMA flash attention ==================
// smem tile layout per buffer: phi [128 keys][16 dims] rows padded to 48B,
//                              V   [128 keys][32 ch]   rows padded to 80B.
#define PHI_BYTES (128*48)
#define TILE_BYTES (PHI_BYTES + 128*80)

__device__ __forceinline__ void load_tile(u32 bufb, int b, int k0, int tid) {
    u32 pdst = bufb + (u32)tid*48;
    const char* psrc = (const char*)(g_Pb + ((size_t)b*NN + k0 + tid)*8);
    cp16(pdst, psrc); cp16(pdst + 16, psrc + 16);
    u32 vdst = bufb + PHI_BYTES + (u32)tid*80;
    const char* vsrc = (const char*)(g_Gv + ((size_t)b*NN + k0 + tid)*32);
    #pragma unroll
    for (int i = 0; i < 4; i++) cp16(vdst + 16*i, vsrc + 16*i);
}

__global__ __launch_bounds__(128, 3) void attn_kernel()
{
    __shared__ __align__(16) char smbuf[2][TILE_BYTES];
    __shared__ unsigned itemSlot;

    int tid  = threadIdx.x;
    int wid  = tid >> 5;
    int lane = tid & 31;
    int g = lane >> 2, t = lane & 3;
    u32 sb0 = smem_u32(smbuf[0]);
    u32 sb1 = smem_u32(smbuf[1]);

    // per-lane ldmatrix addresses (relative offsets, buffer base added later)
    u32 phi_off = (u32)((((lane>>4)&1)*8 + (lane&7))*48 + ((lane>>3)&1)*16);
    u32 v_off   = (u32)((((lane>>3)&1)*8 + (lane&7))*80 + ((lane>>4)&1)*16);

    for (;;) {
        __syncthreads();                        // smem safe to reuse
        if (tid == 0) itemSlot = atomicAdd(&g_ctr, 1u);
        __syncthreads();
        unsigned item = itemSlot;
        if (item >= NITEMS) break;

        int kc = item % KSP;
        int bqt = item / KSP;
        int b = bqt & 1, qt = bqt >> 1;
        int q0w = qt*128 + wid*32;
        int k0 = kc * 256;

        load_tile(sb0, b, k0, tid);       CP_COMMIT();
        load_tile(sb1, b, k0 + 128, tid); CP_COMMIT();

        // Q A-fragments (2 m-tiles)
        u32 qa[2][4];
        #pragma unroll
        for (int m = 0; m < 2; m++) {
            const u32* t0 = g_Tb + ((size_t)b*NN + q0w + m*16 + g)*8;
            const u32* t8 = t0 + 8*8;
            qa[m][0] = t0[t];     qa[m][1] = t8[t];
            qa[m][2] = t0[t + 4]; qa[m][3] = t8[t + 4];
        }

        float y[2][4][4];
        #pragma unroll
        for (int m = 0; m < 2; m++)
            #pragma unroll
            for (int nt = 0; nt < 4; nt++)
                #pragma unroll
                for (int d = 0; d < 4; d++) y[m][nt][d] = 0.0f;
        ull ws[4] = {0ull, 0ull, 0ull, 0ull};

        CP_WAIT(1);
        __syncthreads();

        #pragma unroll
        for (int t2 = 0; t2 < 2; t2++) {
            u32 bufb = t2 ? sb1 : sb0;
            u32 phibase = bufb + phi_off;
            u32 vbase   = bufb + PHI_BYTES + v_off;

            #pragma unroll
            for (int kq4 = 0; kq4 < 4; kq4++) {       // 32-key quarters
                int kq = kq4 * 32;
                // phi B-fragments for 4 n-tiles
                u32 pb[4][2];
                ldsm_x4(pb[0][0], pb[0][1], pb[1][0], pb[1][1],
                        phibase + (u32)(kq)*48);
                ldsm_x4(pb[2][0], pb[2][1], pb[3][0], pb[3][1],
                        phibase + (u32)(kq + 16)*48);

                // S = Q * phi^T
                float S[2][4][4];
                #pragma unroll
                for (int m = 0; m < 2; m++)
                    #pragma unroll
                    for (int j = 0; j < 4; j++) {
                        S[m][j][0] = S[m][j][1] = S[m][j][2] = S[m][j][3] = 0.0f;
                        mma_bf16(S[m][j], qa[m], pb[j]);
                    }

                // exp + wsum + pack P A-fragments
                u32 pa[2][2][4];
                #pragma unroll
                for (int m = 0; m < 2; m++)
                    #pragma unroll
                    for (int j = 0; j < 4; j++) {
                        ull p01, p23;
                        asm("mov.b64 %0,{%1,%2};" : "=l"(p01)
                            : "f"(S[m][j][0]), "f"(S[m][j][1]));
                        asm("mov.b64 %0,{%1,%2};" : "=l"(p23)
                            : "f"(S[m][j][2]), "f"(S[m][j][3]));
                        ull e01 = fexp2(p01);
                        ull e23 = fexp2(p23);
                        ws[m*2 + 0] = add2(ws[m*2 + 0], e01);
                        ws[m*2 + 1] = add2(ws[m*2 + 1], e23);
                        int c = j >> 1;
                        if ((j & 1) == 0) {
                            pa[m][c][0] = packbf(e01);
                            pa[m][c][1] = packbf(e23);
                        } else {
                            pa[m][c][2] = packbf(e01);
                            pa[m][c][3] = packbf(e23);
                        }
                    }

                // MMA2: y += P * V for the two 16-key chunks
                #pragma unroll
                for (int c = 0; c < 2; c++) {
                    u32 vb[4][2];
                    ldsm_x4t(vb[0][0], vb[0][1], vb[1][0], vb[1][1],
                             vbase + (u32)(kq + c*16)*80);
                    ldsm_x4t(vb[2][0], vb[2][1], vb[3][0], vb[3][1],
                             vbase + (u32)(kq + c*16)*80 + 32);
                    #pragma unroll
                    for (int m = 0; m < 2; m++)
                        #pragma unroll
                        for (int nt = 0; nt < 4; nt++)
                            mma_bf16(y[m][nt], pa[m][c], vb[nt]);
                }
            }
            if (t2 == 0) { CP_WAIT(0); __syncthreads(); }
        }

        // ---- write partials ----
        float* part = g_part + ((size_t)(kc*BB + b)*33)*NN;
        #pragma unroll
        for (int m = 0; m < 2; m++) {
            int rg = q0w + m*16 + g;
            #pragma unroll
            for (int nt = 0; nt < 4; nt++) {
                int ch = nt*8 + 2*t;
                part[(size_t)ch*NN + rg]       = y[m][nt][0];
                part[(size_t)(ch+1)*NN + rg]   = y[m][nt][1];
                part[(size_t)ch*NN + rg+8]     = y[m][nt][2];
                part[(size_t)(ch+1)*NN + rg+8] = y[m][nt][3];
            }
        }
        #pragma unroll
        for (int i = 0; i < 4; i++) {
            float v = __uint_as_float((u32)ws[i])
                    + __uint_as_float((u32)(ws[i] >> 32));
            v += __shfl_xor_sync(0xFFFFFFFFu, v, 1);
            v += __shfl_xor_sync(0xFFFFFFFFu, v, 2);
            if (t == 0) {
                int row = q0w + (i >> 1)*16 + (i & 1)*8 + g;
                part[(size_t)32*NN + row] = v;
            }
        }
    }
}

// ================== Phase 3: combine + folded BN + residual ==================
__global__ __launch_bounds__(128) void epi_kernel(
    const float* __restrict__ bfimg, const float* __restrict__ x,
    const float* __restrict__ w_W,   const float* __restrict__ b_W,
    const float* __restrict__ gamma, const float* __restrict__ beta,
    const float* __restrict__ mean,  const float* __restrict__ var,
    float* __restrict__ out)
{
    __shared__ __align__(16) float Wp[32*CI];
    __shared__ float bp[32];
    int tid = threadIdx.x;
    int half = blockIdx.z;
    int cbase = half * 32;
    if (tid < 32) {
        int c = cbase + tid;
        float inv = rsqrtf(var[c] + 1e-5f);
        float al  = gamma[c] * inv;
        bp[tid]   = beta[c] + al * (b_W[c] - mean[c]);
    }
    for (int idx = tid; idx < 32*CI; idx += 128) {
        int c = cbase + idx / CI;
        float inv = rsqrtf(var[c] + 1e-5f);
        Wp[idx] = gamma[c] * inv * w_W[c*CI + (idx % CI)];
    }
    __syncthreads();

    int b = blockIdx.y;
    int n = blockIdx.x * 128 + tid;

    float y[32];
    float ws = 0.0f;
    #pragma unroll
    for (int j = 0; j < 32; j++) y[j] = 0.0f;
    for (int ksi = 0; ksi < KSP; ksi++) {
        const float* base = g_part + ((size_t)(ksi*BB + b)*33)*NN + n;
        #pragma unroll
        for (int j = 0; j < 32; j++) y[j] += base[(size_t)j*NN];
        ws += base[(size_t)32*NN];
    }
    float invws = 1.0f / ws;
    #pragma unroll
    for (int j = 0; j < 32; j++) y[j] *= invws;

    const float* xr = x     + (size_t)b*CC*NN + n;
    const float* br = bfimg + (size_t)b*CC*NN + n;
    float* o1 = out + (size_t)b*2*CC*NN + n;
    float* o2 = o1 + (size_t)CC*NN;

    for (int ci = 0; ci < 32; ci++) {
        int c = cbase + ci;
        const float4* w4 = (const float4*)&Wp[ci*CI];
        float4 wa = w4[0], wb = w4[1], wc = w4[2], wd = w4[3];
        float base = bp[ci];
        float r1 = base + xr[(size_t)c*NN];
        float r2 = base + br[(size_t)c*NN];
        r1 = fmaf(wa.x, y[0],  r1); r1 = fmaf(wa.y, y[1],  r1);
        r1 = fmaf(wa.z, y[2],  r1); r1 = fmaf(wa.w, y[3],  r1);
        r1 = fmaf(wb.x, y[4],  r1); r1 = fmaf(wb.y, y[5],  r1);
        r1 = fmaf(wb.z, y[6],  r1); r1 = fmaf(wb.w, y[7],  r1);
        r1 = fmaf(wc.x, y[8],  r1); r1 = fmaf(wc.y, y[9],  r1);
        r1 = fmaf(wc.z, y[10], r1); r1 = fmaf(wc.w, y[11], r1);
        r1 = fmaf(wd.x, y[12], r1); r1 = fmaf(wd.y, y[13], r1);
        r1 = fmaf(wd.z, y[14], r1); r1 = fmaf(wd.w, y[15], r1);
        r2 = fmaf(wa.x, y[16], r2); r2 = fmaf(wa.y, y[17], r2);
        r2 = fmaf(wa.z, y[18], r2); r2 = fmaf(wa.w, y[19], r2);
        r2 = fmaf(wb.x, y[20], r2); r2 = fmaf(wb.y, y[21], r2);
        r2 = fmaf(wb.z, y[22], r2); r2 = fmaf(wb.w, y[23], r2);
        r2 = fmaf(wc.x, y[24], r2); r2 = fmaf(wc.y, y[25], r2);
        r2 = fmaf(wc.z, y[26], r2); r2 = fmaf(wc.w, y[27], r2);
        r2 = fmaf(wd.x, y[28], r2); r2 = fmaf(wd.y, y[29], r2);
        r2 = fmaf(wd.z, y[30], r2); r2 = fmaf(wd.w, y[31], r2);
        o1[(size_t)c*NN] = r1;
        o2[(size_t)c*NN] = r2;
    }
}

__global__ void reset_kernel() { g_ctr = 0u; }

extern "C" void kernel_launch(void* const* d_in, const int* in_sizes, int n_in,
                              void* d_out, int out_size)
{
    (void)in_sizes; (void)n_in; (void)out_size;
    const float* bfimg   = (const float*)d_in[0];
    const float* x       = (const float*)d_in[1];
    const float* w_theta = (const float*)d_in[2];
    const float* b_theta = (const float*)d_in[3];
    const float* w_phi   = (const float*)d_in[4];
    const float* b_phi   = (const float*)d_in[5];
    const float* w_g     = (const float*)d_in[6];
    const float* b_g     = (const float*)d_in[7];
    const float* w_gbf   = (const float*)d_in[8];
    const float* b_gbf   = (const float*)d_in[9];
    const float* w_W     = (const float*)d_in[10];
    const float* b_W     = (const float*)d_in[11];
    const float* gamma   = (const float*)d_in[12];
    const float* beta    = (const float*)d_in[13];
    const float* mean    = (const float*)d_in[14];
    const float* var     = (const float*)d_in[15];
    float* out = (float*)d_out;

    reset_kernel<<<1, 1>>>();

    dim3 g1(NN/32, BB);
    proj_kernel<<<g1, 128>>>(bfimg, x, w_theta, b_theta, w_phi, b_phi,
                             w_g, b_g, w_gbf, b_gbf);

    attn_kernel<<<ATTN_BLOCKS, 128>>>();

    dim3 g3(NN/128, BB, 2);
    epi_kernel<<<g3, 128>>>(bfimg, x, w_W, b_W, gamma, beta, mean, var, out);
}

// round 5
// speedup vs baseline: 4.0569x; 1.3063x over previous
#include <cuda_runtime.h>
#include <cuda_bf16.h>
#include <cstdint>

#define BB 2
#define CC 64
#define CI 16
#define NN 6400            // 80*80
#define KSP 25             // partial slots (key chunks of 256)
#define NITEMS 2500        // 50 qtiles * 2 batches * 25 kchunks
#define ATTN_BLOCKS 456    // 3 per SM (152 SMs on GB300)

typedef unsigned long long ull;
typedef unsigned int u32;

// ---- global scratch (no allocations allowed) ----
__device__ u32  g_Tb[BB*NN*8];              // theta bf16x2 words [b][q][8]
__device__ u32  g_Pb[BB*NN*8];              // phi   bf16x2 words [b][k][8]
__device__ __nv_bfloat16 g_Gv[(size_t)BB*NN*32]; // values [b][n][32ch]
__device__ float g_part[(size_t)KSP*BB*33*NN];   // partials acc(32)+wsum
__device__ float g_ysum[(size_t)BB*33*NN];       // reduced partials
__device__ unsigned g_ctr;

// =================== low-level helpers ===================
__device__ __forceinline__ u32 smem_u32(const void* p) {
    u32 a; asm("{ .reg .u64 t; cvta.to.shared.u64 t, %1; cvt.u32.u64 %0, t; }"
               : "=r"(a) : "l"(p));
    return a;
}
__device__ __forceinline__ void cp16(u32 dst, const void* src) {
    asm volatile("cp.async.cg.shared.global [%0], [%1], 16;" :: "r"(dst), "l"(src));
}
#define CP_COMMIT() asm volatile("cp.async.commit_group;" ::: "memory")
#define CP_WAIT(n)  asm volatile("cp.async.wait_group %0;" :: "n"(n) : "memory")

__device__ __forceinline__ void ldsm_x4(u32& r0, u32& r1, u32& r2, u32& r3, u32 a) {
    asm volatile("ldmatrix.sync.aligned.m8n8.x4.shared.b16 {%0,%1,%2,%3}, [%4];"
                 : "=r"(r0), "=r"(r1), "=r"(r2), "=r"(r3) : "r"(a));
}
__device__ __forceinline__ void ldsm_x4t(u32& r0, u32& r1, u32& r2, u32& r3, u32 a) {
    asm volatile("ldmatrix.sync.aligned.m8n8.x4.trans.shared.b16 {%0,%1,%2,%3}, [%4];"
                 : "=r"(r0), "=r"(r1), "=r"(r2), "=r"(r3) : "r"(a));
}
__device__ __forceinline__ void mma_bf16(float* d, const u32* a, const u32* b) {
    asm volatile(
        "mma.sync.aligned.m16n8k16.row.col.f32.bf16.bf16.f32 "
        "{%0,%1,%2,%3}, {%4,%5,%6,%7}, {%8,%9}, {%0,%1,%2,%3};"
        : "+f"(d[0]), "+f"(d[1]), "+f"(d[2]), "+f"(d[3])
        : "r"(a[0]), "r"(a[1]), "r"(a[2]), "r"(a[3]), "r"(b[0]), "r"(b[1]));
}

// ---------------- f32x2 packed fast exp ----------------
__device__ __forceinline__ ull fma2(ull a, ull b, ull c) {
    ull d; asm("fma.rn.f32x2 %0,%1,%2,%3;" : "=l"(d) : "l"(a), "l"(b), "l"(c)); return d;
}
__device__ __forceinline__ ull mul2(ull a, ull b) {
    ull d; asm("mul.rn.f32x2 %0,%1,%2;" : "=l"(d) : "l"(a), "l"(b)); return d;
}
__device__ __forceinline__ ull add2(ull a, ull b) {
    ull d; asm("add.rn.f32x2 %0,%1,%2;" : "=l"(d) : "l"(a), "l"(b)); return d;
}
__device__ __forceinline__ ull pk2(float f) {
    unsigned u = __float_as_uint(f); return ((ull)u << 32) | u;
}
__device__ __forceinline__ ull fexp2(ull s) {
    ull t  = mul2(s, pk2(1.4426950408889634f));
    ull kf = add2(t, pk2(12582912.0f));
    ull nf = add2(kf, pk2(-12582912.0f));
    ull r  = fma2(nf, pk2(-0.69314718055994531f), s);
    ull q  = pk2(8.3333333e-3f);
    q = fma2(q, r, pk2(4.1666666e-2f));
    q = fma2(q, r, pk2(1.6666666e-1f));
    q = fma2(q, r, pk2(0.5f));
    q = fma2(q, r, pk2(1.0f));
    ull e = fma2(q, r, pk2(1.0f));
    unsigned klo = (unsigned)kf, khi = (unsigned)(kf >> 32);
    unsigned slo = (klo << 23) + 0x3F800000u;
    unsigned shi = (khi << 23) + 0x3F800000u;
    return mul2(e, ((ull)shi << 32) | slo);
}
// pack f32x2 (lo,hi) -> bf16x2 word {lo | hi<<16}
__device__ __forceinline__ u32 packbf(ull e2) {
    u32 lo, hi, w;
    asm("mov.b64 {%0,%1}, %2;" : "=r"(lo), "=r"(hi) : "l"(e2));
    asm("cvt.rn.bf16x2.f32 %0, %1, %2;"
        : "=r"(w) : "f"(__uint_as_float(hi)), "f"(__uint_as_float(lo)));
    return w;
}

// ================== Phase 1: projections (bf16 out) ==================
__global__ __launch_bounds__(128) void proj_kernel(
    const float* __restrict__ bfimg, const float* __restrict__ x,
    const float* __restrict__ w_theta, const float* __restrict__ b_theta,
    const float* __restrict__ w_phi,   const float* __restrict__ b_phi,
    const float* __restrict__ w_g,     const float* __restrict__ b_g,
    const float* __restrict__ w_gbf,   const float* __restrict__ b_gbf)
{
    __shared__ __align__(16) float wS[4][CC*CI];
    __shared__ __align__(16) float sB[CC*32];
    __shared__ __align__(16) float sX[CC*32];
    int tid = threadIdx.x;
    for (int idx = tid; idx < CC*CI; idx += 128) {
        int i = idx / CC, c = idx % CC;
        wS[0][c*CI+i] = w_theta[idx];
        wS[1][c*CI+i] = w_phi[idx];
        wS[2][c*CI+i] = w_g[idx];
        wS[3][c*CI+i] = w_gbf[idx];
    }
    int b  = blockIdx.y;
    int n0 = blockIdx.x * 32;
    {
        const float4* gb = (const float4*)(bfimg + (size_t)b*CC*NN + n0);
        const float4* gx = (const float4*)(x     + (size_t)b*CC*NN + n0);
        #pragma unroll
        for (int k = 0; k < 4; k++) {
            int idx = tid + k*128;
            int c = idx >> 3, f = idx & 7;
            ((float4*)sB)[c*8 + f] = gb[(size_t)c*(NN/4) + f];
            ((float4*)sX)[c*8 + f] = gx[(size_t)c*(NN/4) + f];
        }
    }
    __syncthreads();

    int w = tid >> 5, lane = tid & 31;
    int n = n0 + lane;
    const float* src  = (w == 2) ? sX : sB;
    const float* bias = (w == 0) ? b_theta : (w == 1) ? b_phi : (w == 2) ? b_g : b_gbf;
    const float* wm   = wS[w];

    float a[CI];
    #pragma unroll
    for (int i = 0; i < CI; i++) a[i] = bias[i];
    #pragma unroll 8
    for (int c = 0; c < CC; c++) {
        float v = src[c*32 + lane];
        #pragma unroll
        for (int i = 0; i < CI; i++)
            a[i] = fmaf(wm[c*CI+i], v, a[i]);
    }

    u32 words[8];
    #pragma unroll
    for (int i = 0; i < 8; i++)
        asm("cvt.rn.bf16x2.f32 %0, %1, %2;" : "=r"(words[i]) : "f"(a[2*i+1]), "f"(a[2*i]));

    if (w < 2) {
        u32* o = ((w == 0) ? g_Tb : g_Pb) + ((size_t)b*NN + n)*8;
        #pragma unroll
        for (int i = 0; i < 8; i++) o[i] = words[i];
    } else {
        u32* o = (u32*)(g_Gv + ((size_t)b*NN + n)*32) + (w - 2)*8;
        #pragma unroll
        for (int i = 0; i < 8; i++) o[i] = words[i];
    }
}

// ================== Phase 2: HMMA flash attention ==================
#define PHI_BYTES (128*48)
#define TILE_BYTES (PHI_BYTES + 128*80)

__device__ __forceinline__ void load_tile(u32 bufb, int b, int k0, int tid) {
    u32 pdst = bufb + (u32)tid*48;
    const char* psrc = (const char*)(g_Pb + ((size_t)b*NN + k0 + tid)*8);
    cp16(pdst, psrc); cp16(pdst + 16, psrc + 16);
    u32 vdst = bufb + PHI_BYTES + (u32)tid*80;
    const char* vsrc = (const char*)(g_Gv + ((size_t)b*NN + k0 + tid)*32);
    #pragma unroll
    for (int i = 0; i < 4; i++) cp16(vdst + 16*i, vsrc + 16*i);
}

__global__ __launch_bounds__(128, 3) void attn_kernel()
{
    __shared__ __align__(16) char smbuf[2][TILE_BYTES];
    __shared__ unsigned itemSlot;

    int tid  = threadIdx.x;
    int wid  = tid >> 5;
    int lane = tid & 31;
    int g = lane >> 2, t = lane & 3;
    u32 sb0 = smem_u32(smbuf[0]);
    u32 sb1 = smem_u32(smbuf[1]);

    u32 phi_off = (u32)((((lane>>4)&1)*8 + (lane&7))*48 + ((lane>>3)&1)*16);
    u32 v_off   = (u32)((((lane>>3)&1)*8 + (lane&7))*80 + ((lane>>4)&1)*16);

    for (;;) {
        __syncthreads();
        if (tid == 0) itemSlot = atomicAdd(&g_ctr, 1u);
        __syncthreads();
        unsigned item = itemSlot;
        if (item >= NITEMS) break;

        int kc = item % KSP;
        int bqt = item / KSP;
        int b = bqt & 1, qt = bqt >> 1;
        int q0w = qt*128 + wid*32;
        int k0 = kc * 256;

        load_tile(sb0, b, k0, tid);       CP_COMMIT();
        load_tile(sb1, b, k0 + 128, tid); CP_COMMIT();

        u32 qa[2][4];
        #pragma unroll
        for (int m = 0; m < 2; m++) {
            const u32* t0 = g_Tb + ((size_t)b*NN + q0w + m*16 + g)*8;
            const u32* t8 = t0 + 8*8;
            qa[m][0] = t0[t];     qa[m][1] = t8[t];
            qa[m][2] = t0[t + 4]; qa[m][3] = t8[t + 4];
        }

        float y[2][4][4];
        #pragma unroll
        for (int m = 0; m < 2; m++)
            #pragma unroll
            for (int nt = 0; nt < 4; nt++)
                #pragma unroll
                for (int d = 0; d < 4; d++) y[m][nt][d] = 0.0f;
        ull ws[4] = {0ull, 0ull, 0ull, 0ull};

        CP_WAIT(1);
        __syncthreads();

        #pragma unroll
        for (int t2 = 0; t2 < 2; t2++) {
            u32 bufb = t2 ? sb1 : sb0;
            u32 phibase = bufb + phi_off;
            u32 vbase   = bufb + PHI_BYTES + v_off;

            #pragma unroll
            for (int kq4 = 0; kq4 < 4; kq4++) {
                int kq = kq4 * 32;
                u32 pb[4][2];
                ldsm_x4(pb[0][0], pb[0][1], pb[1][0], pb[1][1],
                        phibase + (u32)(kq)*48);
                ldsm_x4(pb[2][0], pb[2][1], pb[3][0], pb[3][1],
                        phibase + (u32)(kq + 16)*48);

                float S[2][4][4];
                #pragma unroll
                for (int m = 0; m < 2; m++)
                    #pragma unroll
                    for (int j = 0; j < 4; j++) {
                        S[m][j][0] = S[m][j][1] = S[m][j][2] = S[m][j][3] = 0.0f;
                        mma_bf16(S[m][j], qa[m], pb[j]);
                    }

                u32 pa[2][2][4];
                #pragma unroll
                for (int m = 0; m < 2; m++)
                    #pragma unroll
                    for (int j = 0; j < 4; j++) {
                        ull p01, p23;
                        asm("mov.b64 %0,{%1,%2};" : "=l"(p01)
                            : "f"(S[m][j][0]), "f"(S[m][j][1]));
                        asm("mov.b64 %0,{%1,%2};" : "=l"(p23)
                            : "f"(S[m][j][2]), "f"(S[m][j][3]));
                        ull e01 = fexp2(p01);
                        ull e23 = fexp2(p23);
                        ws[m*2 + 0] = add2(ws[m*2 + 0], e01);
                        ws[m*2 + 1] = add2(ws[m*2 + 1], e23);
                        int c = j >> 1;
                        if ((j & 1) == 0) {
                            pa[m][c][0] = packbf(e01);
                            pa[m][c][1] = packbf(e23);
                        } else {
                            pa[m][c][2] = packbf(e01);
                            pa[m][c][3] = packbf(e23);
                        }
                    }

                #pragma unroll
                for (int c = 0; c < 2; c++) {
                    u32 vb[4][2];
                    ldsm_x4t(vb[0][0], vb[0][1], vb[1][0], vb[1][1],
                             vbase + (u32)(kq + c*16)*80);
                    ldsm_x4t(vb[2][0], vb[2][1], vb[3][0], vb[3][1],
                             vbase + (u32)(kq + c*16)*80 + 32);
                    #pragma unroll
                    for (int m = 0; m < 2; m++)
                        #pragma unroll
                        for (int nt = 0; nt < 4; nt++)
                            mma_bf16(y[m][nt], pa[m][c], vb[nt]);
                }
            }
            if (t2 == 0) { CP_WAIT(0); __syncthreads(); }
        }

        float* part = g_part + ((size_t)(kc*BB + b)*33)*NN;
        #pragma unroll
        for (int m = 0; m < 2; m++) {
            int rg = q0w + m*16 + g;
            #pragma unroll
            for (int nt = 0; nt < 4; nt++) {
                int ch = nt*8 + 2*t;
                part[(size_t)ch*NN + rg]       = y[m][nt][0];
                part[(size_t)(ch+1)*NN + rg]   = y[m][nt][1];
                part[(size_t)ch*NN + rg+8]     = y[m][nt][2];
                part[(size_t)(ch+1)*NN + rg+8] = y[m][nt][3];
            }
        }
        #pragma unroll
        for (int i = 0; i < 4; i++) {
            float v = __uint_as_float((u32)ws[i])
                    + __uint_as_float((u32)(ws[i] >> 32));
            v += __shfl_xor_sync(0xFFFFFFFFu, v, 1);
            v += __shfl_xor_sync(0xFFFFFFFFu, v, 2);
            if (t == 0) {
                int row = q0w + (i >> 1)*16 + (i & 1)*8 + g;
                part[(size_t)32*NN + row] = v;
            }
        }
    }
}

// ============ Phase 3a: parallel partial reduction ============
// one thread per (b, j, n) element; 25 coalesced strided loads each
__global__ __launch_bounds__(256) void reduce_kernel()
{
    const size_t STR = (size_t)BB*33*NN;
    size_t idx = (size_t)blockIdx.x * 256 + threadIdx.x;   // 0 .. BB*33*NN-1
    const float* p = g_part + idx;
    float v = 0.0f;
    #pragma unroll
    for (int ks = 0; ks < KSP; ks++) v += p[ks*STR];
    g_ysum[idx] = v;
}

// ============ Phase 3b: folded BN(W y) + residual, channel-split ============
__global__ __launch_bounds__(128) void epi_kernel(
    const float* __restrict__ bfimg, const float* __restrict__ x,
    const float* __restrict__ w_W,   const float* __restrict__ b_W,
    const float* __restrict__ gamma, const float* __restrict__ beta,
    const float* __restrict__ mean,  const float* __restrict__ var,
    float* __restrict__ out)
{
    __shared__ __align__(16) float Wp[16*CI];
    __shared__ float bp[16];
    int tid = threadIdx.x;
    int quarter = blockIdx.z;            // 0..3: 16 output channels each
    int cbase = quarter * 16;
    if (tid < 16) {
        int c = cbase + tid;
        float inv = rsqrtf(var[c] + 1e-5f);
        float al  = gamma[c] * inv;
        bp[tid]   = beta[c] + al * (b_W[c] - mean[c]);
    }
    if (tid < 16*CI) {
        int c = cbase + tid / CI;
        float inv = rsqrtf(var[c] + 1e-5f);
        Wp[tid] = gamma[c] * inv * w_W[c*CI + (tid % CI)];
    }
    // 16*CI = 256 > 128 threads: second pass
    if (tid + 128 < 16*CI) {
        int idx = tid + 128;
        int c = cbase + idx / CI;
        float inv = rsqrtf(var[c] + 1e-5f);
        Wp[idx] = gamma[c] * inv * w_W[c*CI + (idx % CI)];
    }
    __syncthreads();

    int b = blockIdx.y;
    int n = blockIdx.x * 128 + tid;

    const float* ys = g_ysum + (size_t)b*33*NN + n;
    float y[32];
    #pragma unroll
    for (int j = 0; j < 32; j++) y[j] = ys[(size_t)j*NN];
    float invws = 1.0f / ys[(size_t)32*NN];
    #pragma unroll
    for (int j = 0; j < 32; j++) y[j] *= invws;

    const float* xr = x     + (size_t)b*CC*NN + n;
    const float* br = bfimg + (size_t)b*CC*NN + n;
    float* o1 = out + (size_t)b*2*CC*NN + n;
    float* o2 = o1 + (size_t)CC*NN;

    #pragma unroll
    for (int ci = 0; ci < 16; ci++) {
        int c = cbase + ci;
        const float4* w4 = (const float4*)&Wp[ci*CI];
        float4 wa = w4[0], wb = w4[1], wc = w4[2], wd = w4[3];
        float base = bp[ci];
        float r1 = base + xr[(size_t)c*NN];
        float r2 = base + br[(size_t)c*NN];
        r1 = fmaf(wa.x, y[0],  r1); r1 = fmaf(wa.y, y[1],  r1);
        r1 = fmaf(wa.z, y[2],  r1); r1 = fmaf(wa.w, y[3],  r1);
        r1 = fmaf(wb.x, y[4],  r1); r1 = fmaf(wb.y, y[5],  r1);
        r1 = fmaf(wb.z, y[6],  r1); r1 = fmaf(wb.w, y[7],  r1);
        r1 = fmaf(wc.x, y[8],  r1); r1 = fmaf(wc.y, y[9],  r1);
        r1 = fmaf(wc.z, y[10], r1); r1 = fmaf(wc.w, y[11], r1);
        r1 = fmaf(wd.x, y[12], r1); r1 = fmaf(wd.y, y[13], r1);
        r1 = fmaf(wd.z, y[14], r1); r1 = fmaf(wd.w, y[15], r1);
        r2 = fmaf(wa.x, y[16], r2); r2 = fmaf(wa.y, y[17], r2);
        r2 = fmaf(wa.z, y[18], r2); r2 = fmaf(wa.w, y[19], r2);
        r2 = fmaf(wb.x, y[20], r2); r2 = fmaf(wb.y, y[21], r2);
        r2 = fmaf(wb.z, y[22], r2); r2 = fmaf(wb.w, y[23], r2);
        r2 = fmaf(wc.x, y[24], r2); r2 = fmaf(wc.y, y[25], r2);
        r2 = fmaf(wc.z, y[26], r2); r2 = fmaf(wc.w, y[27], r2);
        r2 = fmaf(wd.x, y[28], r2); r2 = fmaf(wd.y, y[29], r2);
        r2 = fmaf(wd.z, y[30], r2); r2 = fmaf(wd.w, y[31], r2);
        o1[(size_t)c*NN] = r1;
        o2[(size_t)c*NN] = r2;
    }
}

__global__ void reset_kernel() { g_ctr = 0u; }

extern "C" void kernel_launch(void* const* d_in, const int* in_sizes, int n_in,
                              void* d_out, int out_size)
{
    (void)in_sizes; (void)n_in; (void)out_size;
    const float* bfimg   = (const float*)d_in[0];
    const float* x       = (const float*)d_in[1];
    const float* w_theta = (const float*)d_in[2];
    const float* b_theta = (const float*)d_in[3];
    const float* w_phi   = (const float*)d_in[4];
    const float* b_phi   = (const float*)d_in[5];
    const float* w_g     = (const float*)d_in[6];
    const float* b_g     = (const float*)d_in[7];
    const float* w_gbf   = (const float*)d_in[8];
    const float* b_gbf   = (const float*)d_in[9];
    const float* w_W     = (const float*)d_in[10];
    const float* b_W     = (const float*)d_in[11];
    const float* gamma   = (const float*)d_in[12];
    const float* beta    = (const float*)d_in[13];
    const float* mean    = (const float*)d_in[14];
    const float* var     = (const float*)d_in[15];
    float* out = (float*)d_out;

    reset_kernel<<<1, 1>>>();

    dim3 g1(NN/32, BB);
    proj_kernel<<<g1, 128>>>(bfimg, x, w_theta, b_theta, w_phi, b_phi,
                             w_g, b_g, w_gbf, b_gbf);

    attn_kernel<<<ATTN_BLOCKS, 128>>>();

    reduce_kernel<<<(BB*33*NN)/256, 256>>>();

    dim3 g3(NN/128, BB, 4);
    epi_kernel<<<g3, 128>>>(bfimg, x, w_W, b_W, gamma, beta, mean, var, out);
}